// round 4
// baseline (speedup 1.0000x reference)
#include <cuda_runtime.h>
#include <cuda_bf16.h>
#include <cstdint>

// Problem constants
#define B_  32
#define S_  256
#define D_  17
#define M_  512
#define H_  8
#define DK_ 64
#define NROW  139264          // B*S*D rows of width 512
#define NSAMP 8192            // B*S

// ---------------------------------------------------------------------------
// Scratch (__device__ globals; allocation-free rule)
// ---------------------------------------------------------------------------
__device__ float g_q[(size_t)NROW * M_];
__device__ float g_k[(size_t)NROW * M_];
__device__ float g_v[(size_t)NROW * M_];
__device__ __nv_bfloat16 g_xh[(size_t)NROW * M_];
__device__ __nv_bfloat16 g_xl[(size_t)NROW * M_];
__device__ __nv_bfloat16 g_ch[(size_t)NROW * M_];
__device__ __nv_bfloat16 g_cl[(size_t)NROW * M_];
__device__ __nv_bfloat16 g_wh[4 * 512 * 512];   // Wq,Wk,Wv,Wo hi (rows contiguous)
__device__ __nv_bfloat16 g_wl[4 * 512 * 512];   // lo

// ---------------------------------------------------------------------------
// Helpers
// ---------------------------------------------------------------------------
__device__ __forceinline__ uint32_t smem_u32(const void* p) {
    uint32_t a;
    asm("{ .reg .u64 t; cvta.to.shared.u64 t, %1; cvt.u32.u64 %0, t; }"
        : "=r"(a) : "l"(p));
    return a;
}

__device__ __forceinline__ void cp16(uint32_t dst, const void* src) {
    asm volatile("cp.async.cg.shared.global [%0], [%1], 16;" :: "r"(dst), "l"(src));
}

__device__ __forceinline__ void ldmx4(uint32_t* r, uint32_t addr) {
    asm volatile("ldmatrix.sync.aligned.m8n8.x4.shared.b16 {%0,%1,%2,%3}, [%4];"
                 : "=r"(r[0]), "=r"(r[1]), "=r"(r[2]), "=r"(r[3]) : "r"(addr));
}

__device__ __forceinline__ void mma16816(float* d, const uint32_t* a,
                                         uint32_t b0, uint32_t b1) {
    asm volatile(
        "mma.sync.aligned.m16n8k16.row.col.f32.bf16.bf16.f32 "
        "{%0,%1,%2,%3}, {%4,%5,%6,%7}, {%8,%9}, {%0,%1,%2,%3};"
        : "+f"(d[0]), "+f"(d[1]), "+f"(d[2]), "+f"(d[3])
        : "r"(a[0]), "r"(a[1]), "r"(a[2]), "r"(a[3]), "r"(b0), "r"(b1));
}

// ---------------------------------------------------------------------------
// bf16-split GEMM on HMMA:
//   virtual K = 1536: phases hi.Wh | hi.Wl | lo.Wh
//   BM=128, BN=256, BK=32, 8 warps (2m x 4n), warp tile 64x64, 4 stages.
//   smem rows padded to 80B -> conflict-free ldmatrix.
// MODE 0: fused q/k/v output (select buffer by col tile).
// MODE 1: single output + bias + resid.
// ---------------------------------------------------------------------------
#define STAGES 4
#define KSTEPS 48
#define STAGE_BYTES (384 * 80)          // A(128 rows) + B(256 rows), 80B rows

__device__ __forceinline__ void load_tiles(
    int tid, uint32_t abase, int r0, int c0, int kk,
    const __nv_bfloat16* __restrict__ A, const __nv_bfloat16* __restrict__ B)
{
    // A: 128 rows x 64B = 512 cp16
    #pragma unroll
    for (int t = 0; t < 2; t++) {
        int f   = tid + t * 256;
        int row = f >> 2, ch = f & 3;
        cp16(abase + row * 80 + ch * 16, A + ((size_t)(r0 + row) << 9) + kk + ch * 8);
    }
    // B: 256 rows x 64B = 1024 cp16
    const uint32_t bbase = abase + 128 * 80;
    #pragma unroll
    for (int t = 0; t < 4; t++) {
        int f   = tid + t * 256;
        int row = f >> 2, ch = f & 3;
        cp16(bbase + row * 80 + ch * 16, B + ((size_t)(c0 + row) << 9) + kk + ch * 8);
    }
    asm volatile("cp.async.commit_group;");
}

template<int MODE>
__global__ __launch_bounds__(256, 1)
void gemm_mma(const __nv_bfloat16* __restrict__ Ah,
              const __nv_bfloat16* __restrict__ Al,
              const __nv_bfloat16* __restrict__ Wh,
              const __nv_bfloat16* __restrict__ Wl,
              float* __restrict__ C0, float* __restrict__ C1,
              float* __restrict__ C2,
              const float* __restrict__ bias,
              const float* __restrict__ resid)
{
    extern __shared__ __align__(128) char smem[];

    const int tid = threadIdx.x;
    const int wid = tid >> 5;
    const int lid = tid & 31;
    const int c0 = blockIdx.x << 8;    // col tile (fast dim -> A L2 reuse)
    const int r0 = blockIdx.y << 7;
    const int m0 = (wid & 1) * 64;
    const int n0 = (wid >> 1) * 64;
    const uint32_t sb = smem_u32(smem);

    float acc[4][8][4];
    #pragma unroll
    for (int i = 0; i < 4; i++)
        #pragma unroll
        for (int j = 0; j < 8; j++)
            #pragma unroll
            for (int q = 0; q < 4; q++) acc[i][j][q] = 0.f;

    // Prologue: 3 stages (phase 0: hi.Wh)
    #pragma unroll
    for (int s = 0; s < STAGES - 1; s++)
        load_tiles(tid, sb + s * STAGE_BYTES, r0, c0, s * 32, Ah, Wh);

    const uint32_t a_off = (uint32_t)((m0 + (lid & 15)) * 80 + ((lid >> 4) << 4));
    const uint32_t b_off = (uint32_t)((n0 + (lid & 7) + ((lid >> 4) << 3)) * 80
                                      + (((lid >> 3) & 1) << 4));

    for (int kc = 0; kc < KSTEPS; kc++) {
        const int s = kc % STAGES;
        if (kc < KSTEPS - 2)      asm volatile("cp.async.wait_group 2;");
        else if (kc == KSTEPS - 2) asm volatile("cp.async.wait_group 1;");
        else                       asm volatile("cp.async.wait_group 0;");
        __syncthreads();

        const int pf = kc + STAGES - 1;
        if (pf < KSTEPS) {
            const int ph = pf >> 4;
            const __nv_bfloat16* As = (ph < 2) ? Ah : Al;
            const __nv_bfloat16* Bs = (ph == 1) ? Wl : Wh;
            load_tiles(tid, sb + (pf % STAGES) * STAGE_BYTES, r0, c0,
                       (pf & 15) << 5, As, Bs);
        }

        const uint32_t as = sb + s * STAGE_BYTES;
        const uint32_t bs = as + 128 * 80;

        #pragma unroll
        for (int kt = 0; kt < 2; kt++) {
            uint32_t a[4][4], b[4][4];
            #pragma unroll
            for (int mi = 0; mi < 4; mi++)
                ldmx4(a[mi], as + a_off + (uint32_t)(mi * 16 * 80 + kt * 32));
            #pragma unroll
            for (int nj = 0; nj < 4; nj++)
                ldmx4(b[nj], bs + b_off + (uint32_t)(nj * 16 * 80 + kt * 32));
            #pragma unroll
            for (int mi = 0; mi < 4; mi++)
                #pragma unroll
                for (int ni = 0; ni < 8; ni++)
                    mma16816(acc[mi][ni], a[mi],
                             b[ni >> 1][(ni & 1) * 2], b[ni >> 1][(ni & 1) * 2 + 1]);
        }
    }

    // Epilogue
    float* C;
    int col0;
    if (MODE == 0) {
        const int which = c0 >> 9;
        C = (which == 0) ? C0 : (which == 1) ? C1 : C2;
        col0 = c0 & 511;
    } else {
        C = C0;
        col0 = c0;
    }
    const int g  = lid >> 2;
    const int tg = lid & 3;
    #pragma unroll
    for (int mi = 0; mi < 4; mi++) {
        #pragma unroll
        for (int ni = 0; ni < 8; ni++) {
            const int r = r0 + m0 + mi * 16 + g;
            const int c = col0 + n0 + ni * 8 + tg * 2;
            float2 v0 = make_float2(acc[mi][ni][0], acc[mi][ni][1]);
            float2 v1 = make_float2(acc[mi][ni][2], acc[mi][ni][3]);
            if (MODE == 1) {
                const float2 bb = *(const float2*)(bias + c);
                const float2 q0 = *(const float2*)(resid + ((size_t)r << 9) + c);
                const float2 q1 = *(const float2*)(resid + ((size_t)(r + 8) << 9) + c);
                v0.x += bb.x + q0.x; v0.y += bb.y + q0.y;
                v1.x += bb.x + q1.x; v1.y += bb.y + q1.y;
            }
            *(float2*)(C + ((size_t)r << 9) + c)       = v0;
            *(float2*)(C + ((size_t)(r + 8) << 9) + c) = v1;
        }
    }
}

// ---------------------------------------------------------------------------
// fp32 -> (bf16 hi, bf16 lo) split
// ---------------------------------------------------------------------------
__global__ __launch_bounds__(256)
void split_kernel(const float* __restrict__ in, __nv_bfloat16* __restrict__ hi,
                  __nv_bfloat16* __restrict__ lo, int n4)
{
    int i = blockIdx.x * 256 + threadIdx.x;
    if (i >= n4) return;
    float4 v = ((const float4*)in)[i];
    __nv_bfloat16 h0 = __float2bfloat16(v.x);
    __nv_bfloat16 h1 = __float2bfloat16(v.y);
    __nv_bfloat16 h2 = __float2bfloat16(v.z);
    __nv_bfloat16 h3 = __float2bfloat16(v.w);
    __nv_bfloat162* hp = (__nv_bfloat162*)hi;
    __nv_bfloat162* lp = (__nv_bfloat162*)lo;
    hp[2 * i]     = __nv_bfloat162(h0, h1);
    hp[2 * i + 1] = __nv_bfloat162(h2, h3);
    lp[2 * i]     = __nv_bfloat162(__float2bfloat16(v.x - __bfloat162float(h0)),
                                   __float2bfloat16(v.y - __bfloat162float(h1)));
    lp[2 * i + 1] = __nv_bfloat162(__float2bfloat16(v.z - __bfloat162float(h2)),
                                   __float2bfloat16(v.w - __bfloat162float(h3)));
}

// ---------------------------------------------------------------------------
// Attention: one CTA per sample, all 8 heads resident, 4x4 register tiling.
// smem layout (floats): sq[140*68] sk[140*68] sv[140*68] ss[8*20*20] sp[400]
// ---------------------------------------------------------------------------
#define SQ_OFF 0
#define SK_OFF 9520
#define SV_OFF 19040
#define SS_OFF 28560
#define SP_OFF 31760
#define ATT_SMEM_FLOATS 32160   // 128640 bytes

__global__ __launch_bounds__(256)
void attn_kernel(const float* __restrict__ q, const float* __restrict__ k,
                 const float* __restrict__ v, const float* __restrict__ P,
                 __nv_bfloat16* __restrict__ ch, __nv_bfloat16* __restrict__ cl)
{
    extern __shared__ float sm[];
    const int n = blockIdx.x;
    const int t = threadIdx.x;
    const size_t base = (size_t)n * D_ * M_;

    // Load q,k,v (17x512 each) into [h][d][c] layout, row stride 68
    for (int f = t; f < 2176; f += 256) {
        int d = f >> 7, hc = f & 127;
        int h = hc >> 4, c4 = hc & 15;
        size_t goff = base + (size_t)d * 512 + h * 64 + c4 * 4;
        int soff = (h * 17 + d) * 68 + c4 * 4;
        *(float4*)(sm + SQ_OFF + soff) = *(const float4*)(q + goff);
        *(float4*)(sm + SK_OFF + soff) = *(const float4*)(k + goff);
        *(float4*)(sm + SV_OFF + soff) = *(const float4*)(v + goff);
    }
    for (int f = t; f < 289; f += 256)
        sm[SP_OFF + (f / 17) * 20 + (f % 17)] = P[f];
    __syncthreads();

    // Scores: 8 heads x 25 blocks of 4x4 (d,e padded to 20)
    if (t < 200) {
        const int h = t / 25, blk = t % 25;
        const int d0 = (blk / 5) * 4, e0 = (blk % 5) * 4;
        const float* sq = sm + SQ_OFF + (h * 17 + d0) * 68;
        const float* sk = sm + SK_OFF + (h * 17 + e0) * 68;
        float acc[4][4];
        #pragma unroll
        for (int i = 0; i < 4; i++)
            #pragma unroll
            for (int j = 0; j < 4; j++) acc[i][j] = 0.f;
        #pragma unroll 4
        for (int c4 = 0; c4 < 16; c4++) {
            float4 qa[4], kb[4];
            #pragma unroll
            for (int i = 0; i < 4; i++) qa[i] = *(const float4*)(sq + i * 68 + c4 * 4);
            #pragma unroll
            for (int j = 0; j < 4; j++) kb[j] = *(const float4*)(sk + j * 68 + c4 * 4);
            #pragma unroll
            for (int i = 0; i < 4; i++)
                #pragma unroll
                for (int j = 0; j < 4; j++)
                    acc[i][j] += qa[i].x * kb[j].x + qa[i].y * kb[j].y
                               + qa[i].z * kb[j].z + qa[i].w * kb[j].w;
        }
        float* ss = sm + SS_OFF + h * 400;
        #pragma unroll
        for (int i = 0; i < 4; i++)
            #pragma unroll
            for (int j = 0; j < 4; j++)
                ss[(d0 + i) * 20 + e0 + j] =
                    acc[i][j] * 0.125f + sm[SP_OFF + (d0 + i) * 20 + e0 + j];
    }
    __syncthreads();

    // Softmax: 136 rows
    if (t < 136) {
        float* row = sm + SS_OFF + (t / 17) * 400 + (t % 17) * 20;
        float mx = -1e30f;
        #pragma unroll
        for (int e = 0; e < 17; e++) mx = fmaxf(mx, row[e]);
        float sum = 0.f;
        #pragma unroll
        for (int e = 0; e < 17; e++) {
            float ex = __expf(row[e] - mx);
            row[e] = ex;
            sum += ex;
        }
        float inv = 1.f / sum;
        #pragma unroll
        for (int e = 0; e < 17; e++) row[e] *= inv;
    }
    __syncthreads();

    // ctx: 8 heads x (5 dblk x 16 cblk) of 4x4 -> bf16 hi/lo
    for (int task = t; task < 640; task += 256) {
        const int h = task / 80, rem = task % 80;
        const int d0 = (rem / 16) * 4, c0c = (rem % 16) * 4;
        const float* ss = sm + SS_OFF + h * 400;
        const float* sv = sm + SV_OFF + h * 17 * 68 + c0c;
        float acc[4][4];
        #pragma unroll
        for (int i = 0; i < 4; i++)
            #pragma unroll
            for (int j = 0; j < 4; j++) acc[i][j] = 0.f;
        #pragma unroll 1
        for (int e = 0; e < 17; e++) {
            const float4 vv = *(const float4*)(sv + e * 68);
            #pragma unroll
            for (int i = 0; i < 4; i++) {
                const float w = ss[(d0 + i) * 20 + e];
                acc[i][0] += w * vv.x;
                acc[i][1] += w * vv.y;
                acc[i][2] += w * vv.z;
                acc[i][3] += w * vv.w;
            }
        }
        #pragma unroll
        for (int i = 0; i < 4; i++) {
            const int d = d0 + i;
            if (d < 17) {
                const size_t off = base + (size_t)d * 512 + h * 64 + c0c;
                __nv_bfloat16 hh[4], ll[4];
                #pragma unroll
                for (int j = 0; j < 4; j++) {
                    hh[j] = __float2bfloat16(acc[i][j]);
                    ll[j] = __float2bfloat16(acc[i][j] - __bfloat162float(hh[j]));
                }
                *(uint2*)(ch + off) = *(uint2*)hh;
                *(uint2*)(cl + off) = *(uint2*)ll;
            }
        }
    }
}

// ---------------------------------------------------------------------------
// In-place LayerNorm (warp per row, width 512), eps = 1e-5
// ---------------------------------------------------------------------------
__global__ __launch_bounds__(256)
void ln_kernel(float* __restrict__ out, const float* __restrict__ gamma,
               const float* __restrict__ beta)
{
    const int row  = blockIdx.x * 8 + (threadIdx.x >> 5);
    const int lane = threadIdx.x & 31;
    const size_t base = (size_t)row * 512;

    float4 vals[4];
    float sum = 0.f, sq = 0.f;
    #pragma unroll
    for (int j = 0; j < 4; j++) {
        vals[j] = *(const float4*)(out + base + (size_t)(j * 32 + lane) * 4);
        sum += vals[j].x + vals[j].y + vals[j].z + vals[j].w;
        sq  += vals[j].x * vals[j].x + vals[j].y * vals[j].y
             + vals[j].z * vals[j].z + vals[j].w * vals[j].w;
    }
    #pragma unroll
    for (int o = 16; o > 0; o >>= 1) {
        sum += __shfl_xor_sync(0xffffffffu, sum, o);
        sq  += __shfl_xor_sync(0xffffffffu, sq,  o);
    }
    const float mean = sum * (1.f / 512.f);
    const float var  = sq * (1.f / 512.f) - mean * mean;
    const float rstd = rsqrtf(var + 1e-5f);

    #pragma unroll
    for (int j = 0; j < 4; j++) {
        int c = (j * 32 + lane) * 4;
        float4 g  = *(const float4*)(gamma + c);
        float4 bb = *(const float4*)(beta + c);
        float4 v;
        v.x = (vals[j].x - mean) * rstd * g.x + bb.x;
        v.y = (vals[j].y - mean) * rstd * g.y + bb.y;
        v.z = (vals[j].z - mean) * rstd * g.z + bb.z;
        v.w = (vals[j].w - mean) * rstd * g.w + bb.w;
        *(float4*)(out + base + c) = v;
    }
}

// ---------------------------------------------------------------------------
extern "C" void kernel_launch(void* const* d_in, const int* in_sizes, int n_in,
                              void* d_out, int out_size)
{
    const float* x     = (const float*)d_in[0];
    const float* P     = (const float*)d_in[1];
    const float* Wq    = (const float*)d_in[2];
    const float* Wk    = (const float*)d_in[3];
    const float* Wv    = (const float*)d_in[4];
    const float* Wo    = (const float*)d_in[5];
    const float* bo    = (const float*)d_in[6];
    const float* gamma = (const float*)d_in[7];
    const float* beta  = (const float*)d_in[8];
    float* out = (float*)d_out;

    void *pq, *pk, *pv, *pxh, *pxl, *pch, *pcl, *pwh, *pwl;
    cudaGetSymbolAddress(&pq,  g_q);
    cudaGetSymbolAddress(&pk,  g_k);
    cudaGetSymbolAddress(&pv,  g_v);
    cudaGetSymbolAddress(&pxh, g_xh);
    cudaGetSymbolAddress(&pxl, g_xl);
    cudaGetSymbolAddress(&pch, g_ch);
    cudaGetSymbolAddress(&pcl, g_cl);
    cudaGetSymbolAddress(&pwh, g_wh);
    cudaGetSymbolAddress(&pwl, g_wl);

    __nv_bfloat16* wh = (__nv_bfloat16*)pwh;
    __nv_bfloat16* wl = (__nv_bfloat16*)pwl;

    const int dsm = STAGES * STAGE_BYTES;           // 122880
    cudaFuncSetAttribute(gemm_mma<0>, cudaFuncAttributeMaxDynamicSharedMemorySize, dsm);
    cudaFuncSetAttribute(gemm_mma<1>, cudaFuncAttributeMaxDynamicSharedMemorySize, dsm);
    cudaFuncSetAttribute(attn_kernel, cudaFuncAttributeMaxDynamicSharedMemorySize,
                         ATT_SMEM_FLOATS * 4);      // 128640

    // Weight splits (Wq,Wk,Wv,Wo -> contiguous hi/lo slabs)
    const int nw4 = 512 * 512 / 4;
    split_kernel<<<(nw4 + 255) / 256, 256>>>(Wq, wh + 0 * 262144, wl + 0 * 262144, nw4);
    split_kernel<<<(nw4 + 255) / 256, 256>>>(Wk, wh + 1 * 262144, wl + 1 * 262144, nw4);
    split_kernel<<<(nw4 + 255) / 256, 256>>>(Wv, wh + 2 * 262144, wl + 2 * 262144, nw4);
    split_kernel<<<(nw4 + 255) / 256, 256>>>(Wo, wh + 3 * 262144, wl + 3 * 262144, nw4);
    const int nx4 = (int)((size_t)NROW * 512 / 4);
    split_kernel<<<(nx4 + 255) / 256, 256>>>(x, (__nv_bfloat16*)pxh,
                                             (__nv_bfloat16*)pxl, nx4);

    // Fused QKV projection: N=1536 over contiguous [Wq;Wk;Wv] rows
    dim3 gq(6, NROW / 128);
    gemm_mma<0><<<gq, 256, dsm>>>((const __nv_bfloat16*)pxh, (const __nv_bfloat16*)pxl,
                                  wh, wl,
                                  (float*)pq, (float*)pk, (float*)pv,
                                  nullptr, nullptr);

    attn_kernel<<<NSAMP, 256, ATT_SMEM_FLOATS * 4>>>(
        (const float*)pq, (const float*)pk, (const float*)pv, P,
        (__nv_bfloat16*)pch, (__nv_bfloat16*)pcl);

    // fc_out + bias + residual
    dim3 go(2, NROW / 128);
    gemm_mma<1><<<go, 256, dsm>>>((const __nv_bfloat16*)pch, (const __nv_bfloat16*)pcl,
                                  wh + 3 * 262144, wl + 3 * 262144,
                                  out, nullptr, nullptr, bo, x);

    ln_kernel<<<NROW / 8, 256>>>(out, gamma, beta);
}

// round 5
// speedup vs baseline: 1.2173x; 1.2173x over previous
#include <cuda_runtime.h>
#include <cuda_bf16.h>
#include <cstdint>

// Problem constants
#define B_  32
#define S_  256
#define D_  17
#define M_  512
#define H_  8
#define DK_ 64
#define NROW  139264          // B*S*D rows of width 512
#define NSAMP 8192            // B*S

// ---------------------------------------------------------------------------
// Scratch (__device__ globals; allocation-free rule)
// ---------------------------------------------------------------------------
__device__ float g_q[(size_t)NROW * M_];
__device__ float g_k[(size_t)NROW * M_];
__device__ float g_v[(size_t)NROW * M_];
__device__ __nv_bfloat16 g_xh[(size_t)NROW * M_];
__device__ __nv_bfloat16 g_xl[(size_t)NROW * M_];
__device__ __nv_bfloat16 g_ch[(size_t)NROW * M_];
__device__ __nv_bfloat16 g_cl[(size_t)NROW * M_];
__device__ __nv_bfloat16 g_wh[4 * 512 * 512];   // Wq,Wk,Wv,Wo hi (rows contiguous)
__device__ __nv_bfloat16 g_wl[4 * 512 * 512];   // lo

// ---------------------------------------------------------------------------
// Helpers
// ---------------------------------------------------------------------------
__device__ __forceinline__ uint32_t smem_u32(const void* p) {
    uint32_t a;
    asm("{ .reg .u64 t; cvta.to.shared.u64 t, %1; cvt.u32.u64 %0, t; }"
        : "=r"(a) : "l"(p));
    return a;
}

__device__ __forceinline__ void cp16(uint32_t dst, const void* src) {
    asm volatile("cp.async.cg.shared.global [%0], [%1], 16;" :: "r"(dst), "l"(src));
}

__device__ __forceinline__ void ldmx4(uint32_t* r, uint32_t addr) {
    asm volatile("ldmatrix.sync.aligned.m8n8.x4.shared.b16 {%0,%1,%2,%3}, [%4];"
                 : "=r"(r[0]), "=r"(r[1]), "=r"(r[2]), "=r"(r[3]) : "r"(addr));
}

__device__ __forceinline__ void mma16816(float* d, const uint32_t* a,
                                         uint32_t b0, uint32_t b1) {
    asm volatile(
        "mma.sync.aligned.m16n8k16.row.col.f32.bf16.bf16.f32 "
        "{%0,%1,%2,%3}, {%4,%5,%6,%7}, {%8,%9}, {%0,%1,%2,%3};"
        : "+f"(d[0]), "+f"(d[1]), "+f"(d[2]), "+f"(d[3])
        : "r"(a[0]), "r"(a[1]), "r"(a[2]), "r"(a[3]), "r"(b0), "r"(b1));
}

// ---------------------------------------------------------------------------
// bf16-split GEMM on HMMA:
//   virtual K = 1536: phases hi.Wh | hi.Wl | lo.Wh
//   BM=128, BN=128, BK=32, 128 threads (4 warps, 2m x 2n), warp tile 64x64.
//   3 stages (61.4KB smem) -> 2 CTAs/SM. smem rows 80B -> conflict-free ldmatrix.
// MODE 0: fused q/k/v output (select buffer by col tile). MODE 1: +bias+resid.
// ---------------------------------------------------------------------------
#define STAGES 3
#define KSTEPS 48
#define STAGE_BYTES (256 * 80)          // A(128 rows) + B(128 rows), 80B rows

__device__ __forceinline__ void load_tiles(
    int tid, uint32_t abase, int r0, int c0, int kk,
    const __nv_bfloat16* __restrict__ A, const __nv_bfloat16* __restrict__ B)
{
    // A: 128 rows x 64B = 512 cp16 over 128 threads
    #pragma unroll
    for (int t = 0; t < 4; t++) {
        int f   = tid + t * 128;
        int row = f >> 2, ch = f & 3;
        cp16(abase + row * 80 + ch * 16, A + ((size_t)(r0 + row) << 9) + kk + ch * 8);
    }
    const uint32_t bbase = abase + 128 * 80;
    #pragma unroll
    for (int t = 0; t < 4; t++) {
        int f   = tid + t * 128;
        int row = f >> 2, ch = f & 3;
        cp16(bbase + row * 80 + ch * 16, B + ((size_t)(c0 + row) << 9) + kk + ch * 8);
    }
    asm volatile("cp.async.commit_group;");
}

template<int MODE>
__global__ __launch_bounds__(128)
void gemm_mma(const __nv_bfloat16* __restrict__ Ah,
              const __nv_bfloat16* __restrict__ Al,
              const __nv_bfloat16* __restrict__ Wh,
              const __nv_bfloat16* __restrict__ Wl,
              float* __restrict__ C0, float* __restrict__ C1,
              float* __restrict__ C2,
              const float* __restrict__ bias,
              const float* __restrict__ resid)
{
    extern __shared__ __align__(128) char smem[];

    const int tid = threadIdx.x;
    const int wid = tid >> 5;
    const int lid = tid & 31;
    const int c0 = blockIdx.x << 7;    // col tile (fast dim -> A L2 reuse)
    const int r0 = blockIdx.y << 7;
    const int m0 = (wid & 1) * 64;
    const int n0 = (wid >> 1) * 64;
    const uint32_t sb = smem_u32(smem);

    float acc[4][8][4];
    #pragma unroll
    for (int i = 0; i < 4; i++)
        #pragma unroll
        for (int j = 0; j < 8; j++)
            #pragma unroll
            for (int q = 0; q < 4; q++) acc[i][j][q] = 0.f;

    // Prologue: k-steps 0,1 (phase 0: hi.Wh)
    #pragma unroll
    for (int s = 0; s < STAGES - 1; s++)
        load_tiles(tid, sb + s * STAGE_BYTES, r0, c0, s * 32, Ah, Wh);

    const uint32_t a_off = (uint32_t)((m0 + (lid & 15)) * 80 + ((lid >> 4) << 4));
    const uint32_t b_off = (uint32_t)((n0 + (lid & 7) + ((lid >> 4) << 3)) * 80
                                      + (((lid >> 3) & 1) << 4));

    for (int kc = 0; kc < KSTEPS; kc++) {
        const int s = kc % STAGES;
        if (kc < KSTEPS - 1) asm volatile("cp.async.wait_group 1;");
        else                 asm volatile("cp.async.wait_group 0;");
        __syncthreads();

        const int pf = kc + STAGES - 1;
        if (pf < KSTEPS) {
            const int ph = pf >> 4;
            const __nv_bfloat16* As = (ph < 2) ? Ah : Al;
            const __nv_bfloat16* Bs = (ph == 1) ? Wl : Wh;
            load_tiles(tid, sb + (pf % STAGES) * STAGE_BYTES, r0, c0,
                       (pf & 15) << 5, As, Bs);
        }

        const uint32_t as = sb + s * STAGE_BYTES;
        const uint32_t bs = as + 128 * 80;

        #pragma unroll
        for (int kt = 0; kt < 2; kt++) {
            uint32_t a[4][4], b[4][4];
            #pragma unroll
            for (int mi = 0; mi < 4; mi++)
                ldmx4(a[mi], as + a_off + (uint32_t)(mi * 16 * 80 + kt * 32));
            #pragma unroll
            for (int nj = 0; nj < 4; nj++)
                ldmx4(b[nj], bs + b_off + (uint32_t)(nj * 16 * 80 + kt * 32));
            #pragma unroll
            for (int mi = 0; mi < 4; mi++)
                #pragma unroll
                for (int ni = 0; ni < 8; ni++)
                    mma16816(acc[mi][ni], a[mi],
                             b[ni >> 1][(ni & 1) * 2], b[ni >> 1][(ni & 1) * 2 + 1]);
        }
    }

    // Epilogue
    float* C;
    int col0;
    if (MODE == 0) {
        const int which = c0 >> 9;
        C = (which == 0) ? C0 : (which == 1) ? C1 : C2;
        col0 = c0 & 511;
    } else {
        C = C0;
        col0 = c0;
    }
    const int g  = lid >> 2;
    const int tg = lid & 3;
    #pragma unroll
    for (int mi = 0; mi < 4; mi++) {
        #pragma unroll
        for (int ni = 0; ni < 8; ni++) {
            const int r = r0 + m0 + mi * 16 + g;
            const int c = col0 + n0 + ni * 8 + tg * 2;
            float2 v0 = make_float2(acc[mi][ni][0], acc[mi][ni][1]);
            float2 v1 = make_float2(acc[mi][ni][2], acc[mi][ni][3]);
            if (MODE == 1) {
                const float2 bb = *(const float2*)(bias + c);
                const float2 q0 = *(const float2*)(resid + ((size_t)r << 9) + c);
                const float2 q1 = *(const float2*)(resid + ((size_t)(r + 8) << 9) + c);
                v0.x += bb.x + q0.x; v0.y += bb.y + q0.y;
                v1.x += bb.x + q1.x; v1.y += bb.y + q1.y;
            }
            *(float2*)(C + ((size_t)r << 9) + c)       = v0;
            *(float2*)(C + ((size_t)(r + 8) << 9) + c) = v1;
        }
    }
}

// ---------------------------------------------------------------------------
// fp32 -> (bf16 hi, bf16 lo) split
// ---------------------------------------------------------------------------
__global__ __launch_bounds__(256)
void split_kernel(const float* __restrict__ in, __nv_bfloat16* __restrict__ hi,
                  __nv_bfloat16* __restrict__ lo, int n4)
{
    int i = blockIdx.x * 256 + threadIdx.x;
    if (i >= n4) return;
    float4 v = ((const float4*)in)[i];
    __nv_bfloat16 h0 = __float2bfloat16(v.x);
    __nv_bfloat16 h1 = __float2bfloat16(v.y);
    __nv_bfloat16 h2 = __float2bfloat16(v.z);
    __nv_bfloat16 h3 = __float2bfloat16(v.w);
    __nv_bfloat162* hp = (__nv_bfloat162*)hi;
    __nv_bfloat162* lp = (__nv_bfloat162*)lo;
    hp[2 * i]     = __nv_bfloat162(h0, h1);
    hp[2 * i + 1] = __nv_bfloat162(h2, h3);
    lp[2 * i]     = __nv_bfloat162(__float2bfloat16(v.x - __bfloat162float(h0)),
                                   __float2bfloat16(v.y - __bfloat162float(h1)));
    lp[2 * i + 1] = __nv_bfloat162(__float2bfloat16(v.z - __bfloat162float(h2)),
                                   __float2bfloat16(v.w - __bfloat162float(h3)));
}

// ---------------------------------------------------------------------------
// Attention: one CTA per (sample, 4-head group), 128 threads, 4x4 reg tiling.
// smem floats: sq[4*17*68] sk[...] sv[...] ss[4*400] sp[400] = 15872 (63.5KB)
// ---------------------------------------------------------------------------
#define AQ  0
#define AK  4624
#define AV  9248
#define ASS 13872
#define ASP 15472
#define ATT_SMEM_BYTES (15872 * 4)

__global__ __launch_bounds__(128)
void attn_kernel(const float* __restrict__ q, const float* __restrict__ k,
                 const float* __restrict__ v, const float* __restrict__ P,
                 __nv_bfloat16* __restrict__ ch, __nv_bfloat16* __restrict__ cl)
{
    extern __shared__ float sm[];
    const int n  = blockIdx.x;
    const int hg = blockIdx.y;          // head group: heads hg*4 .. hg*4+3
    const int t  = threadIdx.x;
    const size_t base = (size_t)n * D_ * M_;

    // Load q,k,v for 4 heads: [h][d][c] layout, row stride 68
    for (int f = t; f < 1088; f += 128) {
        int d = f >> 6, hc = f & 63;
        int h = hc >> 4, c4 = hc & 15;
        size_t goff = base + (size_t)d * 512 + (hg * 4 + h) * 64 + c4 * 4;
        int soff = (h * 17 + d) * 68 + c4 * 4;
        *(float4*)(sm + AQ + soff) = *(const float4*)(q + goff);
        *(float4*)(sm + AK + soff) = *(const float4*)(k + goff);
        *(float4*)(sm + AV + soff) = *(const float4*)(v + goff);
    }
    for (int f = t; f < 289; f += 128)
        sm[ASP + (f / 17) * 20 + (f % 17)] = P[f];
    __syncthreads();

    // Scores: 4 heads x 25 blocks of 4x4 = 100 tasks
    if (t < 100) {
        const int h = t / 25, blk = t % 25;
        const int d0 = (blk / 5) * 4, e0 = (blk % 5) * 4;
        const float* sq = sm + AQ + (h * 17 + d0) * 68;
        const float* sk = sm + AK + (h * 17 + e0) * 68;
        float acc[4][4];
        #pragma unroll
        for (int i = 0; i < 4; i++)
            #pragma unroll
            for (int j = 0; j < 4; j++) acc[i][j] = 0.f;
        #pragma unroll 4
        for (int c4 = 0; c4 < 16; c4++) {
            float4 qa[4], kb[4];
            #pragma unroll
            for (int i = 0; i < 4; i++) qa[i] = *(const float4*)(sq + i * 68 + c4 * 4);
            #pragma unroll
            for (int j = 0; j < 4; j++) kb[j] = *(const float4*)(sk + j * 68 + c4 * 4);
            #pragma unroll
            for (int i = 0; i < 4; i++)
                #pragma unroll
                for (int j = 0; j < 4; j++)
                    acc[i][j] += qa[i].x * kb[j].x + qa[i].y * kb[j].y
                               + qa[i].z * kb[j].z + qa[i].w * kb[j].w;
        }
        float* ss = sm + ASS + h * 400;
        #pragma unroll
        for (int i = 0; i < 4; i++)
            #pragma unroll
            for (int j = 0; j < 4; j++)
                ss[(d0 + i) * 20 + e0 + j] =
                    acc[i][j] * 0.125f + sm[ASP + (d0 + i) * 20 + e0 + j];
    }
    __syncthreads();

    // Softmax: 4 heads x 17 rows = 68 tasks
    if (t < 68) {
        float* row = sm + ASS + (t / 17) * 400 + (t % 17) * 20;
        float mx = -1e30f;
        #pragma unroll
        for (int e = 0; e < 17; e++) mx = fmaxf(mx, row[e]);
        float sum = 0.f;
        #pragma unroll
        for (int e = 0; e < 17; e++) {
            float ex = __expf(row[e] - mx);
            row[e] = ex;
            sum += ex;
        }
        float inv = 1.f / sum;
        #pragma unroll
        for (int e = 0; e < 17; e++) row[e] *= inv;
    }
    __syncthreads();

    // ctx: 4 heads x (5 dblk x 16 cblk) = 320 tasks -> bf16 hi/lo
    for (int task = t; task < 320; task += 128) {
        const int h = task / 80, rem = task % 80;
        const int d0 = (rem / 16) * 4, c0c = (rem % 16) * 4;
        const float* ss = sm + ASS + h * 400;
        const float* sv = sm + AV + h * 17 * 68 + c0c;
        float acc[4][4];
        #pragma unroll
        for (int i = 0; i < 4; i++)
            #pragma unroll
            for (int j = 0; j < 4; j++) acc[i][j] = 0.f;
        #pragma unroll 1
        for (int e = 0; e < 17; e++) {
            const float4 vv = *(const float4*)(sv + e * 68);
            #pragma unroll
            for (int i = 0; i < 4; i++) {
                const float w = ss[(d0 + i) * 20 + e];
                acc[i][0] += w * vv.x;
                acc[i][1] += w * vv.y;
                acc[i][2] += w * vv.z;
                acc[i][3] += w * vv.w;
            }
        }
        #pragma unroll
        for (int i = 0; i < 4; i++) {
            const int d = d0 + i;
            if (d < 17) {
                const size_t off = base + (size_t)d * 512 + (hg * 4 + h) * 64 + c0c;
                __nv_bfloat16 hh[4], ll[4];
                #pragma unroll
                for (int j = 0; j < 4; j++) {
                    hh[j] = __float2bfloat16(acc[i][j]);
                    ll[j] = __float2bfloat16(acc[i][j] - __bfloat162float(hh[j]));
                }
                *(uint2*)(ch + off) = *(uint2*)hh;
                *(uint2*)(cl + off) = *(uint2*)ll;
            }
        }
    }
}

// ---------------------------------------------------------------------------
// In-place LayerNorm (warp per row, width 512), eps = 1e-5
// ---------------------------------------------------------------------------
__global__ __launch_bounds__(256)
void ln_kernel(float* __restrict__ out, const float* __restrict__ gamma,
               const float* __restrict__ beta)
{
    const int row  = blockIdx.x * 8 + (threadIdx.x >> 5);
    const int lane = threadIdx.x & 31;
    const size_t base = (size_t)row * 512;

    float4 vals[4];
    float sum = 0.f, sq = 0.f;
    #pragma unroll
    for (int j = 0; j < 4; j++) {
        vals[j] = *(const float4*)(out + base + (size_t)(j * 32 + lane) * 4);
        sum += vals[j].x + vals[j].y + vals[j].z + vals[j].w;
        sq  += vals[j].x * vals[j].x + vals[j].y * vals[j].y
             + vals[j].z * vals[j].z + vals[j].w * vals[j].w;
    }
    #pragma unroll
    for (int o = 16; o > 0; o >>= 1) {
        sum += __shfl_xor_sync(0xffffffffu, sum, o);
        sq  += __shfl_xor_sync(0xffffffffu, sq,  o);
    }
    const float mean = sum * (1.f / 512.f);
    const float var  = sq * (1.f / 512.f) - mean * mean;
    const float rstd = rsqrtf(var + 1e-5f);

    #pragma unroll
    for (int j = 0; j < 4; j++) {
        int c = (j * 32 + lane) * 4;
        float4 g  = *(const float4*)(gamma + c);
        float4 bb = *(const float4*)(beta + c);
        float4 v;
        v.x = (vals[j].x - mean) * rstd * g.x + bb.x;
        v.y = (vals[j].y - mean) * rstd * g.y + bb.y;
        v.z = (vals[j].z - mean) * rstd * g.z + bb.z;
        v.w = (vals[j].w - mean) * rstd * g.w + bb.w;
        *(float4*)(out + base + c) = v;
    }
}

// ---------------------------------------------------------------------------
extern "C" void kernel_launch(void* const* d_in, const int* in_sizes, int n_in,
                              void* d_out, int out_size)
{
    const float* x     = (const float*)d_in[0];
    const float* P     = (const float*)d_in[1];
    const float* Wq    = (const float*)d_in[2];
    const float* Wk    = (const float*)d_in[3];
    const float* Wv    = (const float*)d_in[4];
    const float* Wo    = (const float*)d_in[5];
    const float* bo    = (const float*)d_in[6];
    const float* gamma = (const float*)d_in[7];
    const float* beta  = (const float*)d_in[8];
    float* out = (float*)d_out;

    void *pq, *pk, *pv, *pxh, *pxl, *pch, *pcl, *pwh, *pwl;
    cudaGetSymbolAddress(&pq,  g_q);
    cudaGetSymbolAddress(&pk,  g_k);
    cudaGetSymbolAddress(&pv,  g_v);
    cudaGetSymbolAddress(&pxh, g_xh);
    cudaGetSymbolAddress(&pxl, g_xl);
    cudaGetSymbolAddress(&pch, g_ch);
    cudaGetSymbolAddress(&pcl, g_cl);
    cudaGetSymbolAddress(&pwh, g_wh);
    cudaGetSymbolAddress(&pwl, g_wl);

    __nv_bfloat16* wh = (__nv_bfloat16*)pwh;
    __nv_bfloat16* wl = (__nv_bfloat16*)pwl;

    const int dsm = STAGES * STAGE_BYTES;           // 61440
    cudaFuncSetAttribute(gemm_mma<0>, cudaFuncAttributeMaxDynamicSharedMemorySize, dsm);
    cudaFuncSetAttribute(gemm_mma<1>, cudaFuncAttributeMaxDynamicSharedMemorySize, dsm);
    cudaFuncSetAttribute(attn_kernel, cudaFuncAttributeMaxDynamicSharedMemorySize,
                         ATT_SMEM_BYTES);           // 63488

    // Weight splits (Wq,Wk,Wv,Wo -> contiguous hi/lo slabs)
    const int nw4 = 512 * 512 / 4;
    split_kernel<<<(nw4 + 255) / 256, 256>>>(Wq, wh + 0 * 262144, wl + 0 * 262144, nw4);
    split_kernel<<<(nw4 + 255) / 256, 256>>>(Wk, wh + 1 * 262144, wl + 1 * 262144, nw4);
    split_kernel<<<(nw4 + 255) / 256, 256>>>(Wv, wh + 2 * 262144, wl + 2 * 262144, nw4);
    split_kernel<<<(nw4 + 255) / 256, 256>>>(Wo, wh + 3 * 262144, wl + 3 * 262144, nw4);
    const int nx4 = (int)((size_t)NROW * 512 / 4);
    split_kernel<<<(nx4 + 255) / 256, 256>>>(x, (__nv_bfloat16*)pxh,
                                             (__nv_bfloat16*)pxl, nx4);

    // Fused QKV projection: 12 col tiles over contiguous [Wq;Wk;Wv] rows
    dim3 gq(12, NROW / 128);
    gemm_mma<0><<<gq, 128, dsm>>>((const __nv_bfloat16*)pxh, (const __nv_bfloat16*)pxl,
                                  wh, wl,
                                  (float*)pq, (float*)pk, (float*)pv,
                                  nullptr, nullptr);

    dim3 ga(NSAMP, 2);
    attn_kernel<<<ga, 128, ATT_SMEM_BYTES>>>(
        (const float*)pq, (const float*)pk, (const float*)pv, P,
        (__nv_bfloat16*)pch, (__nv_bfloat16*)pcl);

    // fc_out + bias + residual
    dim3 go(4, NROW / 128);
    gemm_mma<1><<<go, 128, dsm>>>((const __nv_bfloat16*)pch, (const __nv_bfloat16*)pcl,
                                  wh + 3 * 262144, wl + 3 * 262144,
                                  out, nullptr, nullptr, bo, x);

    ln_kernel<<<NROW / 8, 256>>>(out, gamma, beta);
}

// round 6
// speedup vs baseline: 1.3314x; 1.0937x over previous
#include <cuda_runtime.h>
#include <cuda_bf16.h>
#include <cstdint>

// Problem constants
#define B_  32
#define S_  256
#define D_  17
#define M_  512
#define H_  8
#define DK_ 64
#define NROW  139264          // B*S*D rows of width 512
#define NSAMP 8192            // B*S

// ---------------------------------------------------------------------------
// Scratch (__device__ globals; allocation-free rule)
// ---------------------------------------------------------------------------
__device__ float g_q[(size_t)NROW * M_];
__device__ float g_k[(size_t)NROW * M_];
__device__ float g_v[(size_t)NROW * M_];
__device__ __nv_bfloat16 g_xh[(size_t)NROW * M_];
__device__ __nv_bfloat16 g_xl[(size_t)NROW * M_];
__device__ __nv_bfloat16 g_ch[(size_t)NROW * M_];
__device__ __nv_bfloat16 g_cl[(size_t)NROW * M_];
__device__ __nv_bfloat16 g_wh[4 * 512 * 512];   // Wq,Wk,Wv,Wo hi (rows contiguous)
__device__ __nv_bfloat16 g_wl[4 * 512 * 512];   // lo

// ---------------------------------------------------------------------------
// Helpers
// ---------------------------------------------------------------------------
__device__ __forceinline__ uint32_t smem_u32(const void* p) {
    uint32_t a;
    asm("{ .reg .u64 t; cvta.to.shared.u64 t, %1; cvt.u32.u64 %0, t; }"
        : "=r"(a) : "l"(p));
    return a;
}

__device__ __forceinline__ void cp16(uint32_t dst, const void* src) {
    asm volatile("cp.async.cg.shared.global [%0], [%1], 16;" :: "r"(dst), "l"(src));
}

__device__ __forceinline__ void ldmx4(uint32_t* r, uint32_t addr) {
    asm volatile("ldmatrix.sync.aligned.m8n8.x4.shared.b16 {%0,%1,%2,%3}, [%4];"
                 : "=r"(r[0]), "=r"(r[1]), "=r"(r[2]), "=r"(r[3]) : "r"(addr));
}

__device__ __forceinline__ void mma16816(float* d, const uint32_t* a,
                                         uint32_t b0, uint32_t b1) {
    asm volatile(
        "mma.sync.aligned.m16n8k16.row.col.f32.bf16.bf16.f32 "
        "{%0,%1,%2,%3}, {%4,%5,%6,%7}, {%8,%9}, {%0,%1,%2,%3};"
        : "+f"(d[0]), "+f"(d[1]), "+f"(d[2]), "+f"(d[3])
        : "r"(a[0]), "r"(a[1]), "r"(a[2]), "r"(a[3]), "r"(b0), "r"(b1));
}

// Packed fp32x2 FMA (PTX ISA 8.6, sm_100 base)
__device__ __forceinline__ unsigned long long fma2(unsigned long long a,
                                                   unsigned long long b,
                                                   unsigned long long c) {
    unsigned long long d;
    asm("fma.rn.f32x2 %0, %1, %2, %3;" : "=l"(d) : "l"(a), "l"(b), "l"(c));
    return d;
}
__device__ __forceinline__ unsigned long long pack2(float x, float y) {
    unsigned long long d;
    asm("mov.b64 %0, {%1, %2};" : "=l"(d) : "f"(x), "f"(y));
    return d;
}
__device__ __forceinline__ float2 unpack2(unsigned long long v) {
    float x, y;
    asm("mov.b64 {%0, %1}, %2;" : "=f"(x), "=f"(y) : "l"(v));
    return make_float2(x, y);
}

// ---------------------------------------------------------------------------
// bf16-split GEMM on HMMA, fused-phase structure:
//   pass A (iters 0-7):  acc += xh.Wh + xh.Wl   (A LDSM shared by both B's)
//   pass B (iters 8-15): acc += xl.Wh
// BM=BN=128, BK=64 per iter, 128 threads (4 warps 2x2), warp tile 64x64.
// 2-stage cp.async double buffer; rows padded to 144B (conflict-free ldmatrix).
// MODE 0: fused q/k/v output (select by col tile). MODE 1: +bias+resid.
// ---------------------------------------------------------------------------
#define ITERS 16
#define ROWB 144
#define STAGE_BYTES (384 * ROWB)    // A(128) + B0(128) + B1(128) rows

__device__ __forceinline__ void load_iter(
    int tid, uint32_t sbase, int r0, int c0, int it,
    const __nv_bfloat16* __restrict__ xh, const __nv_bfloat16* __restrict__ xl,
    const __nv_bfloat16* __restrict__ Wh, const __nv_bfloat16* __restrict__ Wl)
{
    const int kk = (it & 7) * 64;
    const __nv_bfloat16* A = (it < 8) ? xh : xl;
    #pragma unroll
    for (int t = 0; t < 8; t++) {                 // A: 128 rows x 128B
        int f = tid + t * 128;
        int row = f >> 3, ch = f & 7;
        cp16(sbase + row * ROWB + ch * 16, A + ((size_t)(r0 + row) << 9) + kk + ch * 8);
    }
    const uint32_t b0 = sbase + 128 * ROWB;
    #pragma unroll
    for (int t = 0; t < 8; t++) {                 // B0 = Wh
        int f = tid + t * 128;
        int row = f >> 3, ch = f & 7;
        cp16(b0 + row * ROWB + ch * 16, Wh + ((size_t)(c0 + row) << 9) + kk + ch * 8);
    }
    if (it < 8) {
        const uint32_t b1 = sbase + 256 * ROWB;
        #pragma unroll
        for (int t = 0; t < 8; t++) {             // B1 = Wl (pass A only)
            int f = tid + t * 128;
            int row = f >> 3, ch = f & 7;
            cp16(b1 + row * ROWB + ch * 16, Wl + ((size_t)(c0 + row) << 9) + kk + ch * 8);
        }
    }
    asm volatile("cp.async.commit_group;");
}

template<int MODE>
__global__ __launch_bounds__(128)
void gemm_mma(const __nv_bfloat16* __restrict__ Ah,
              const __nv_bfloat16* __restrict__ Al,
              const __nv_bfloat16* __restrict__ Wh,
              const __nv_bfloat16* __restrict__ Wl,
              float* __restrict__ C0, float* __restrict__ C1,
              float* __restrict__ C2,
              const float* __restrict__ bias,
              const float* __restrict__ resid)
{
    extern __shared__ __align__(128) char smem[];

    const int tid = threadIdx.x;
    const int wid = tid >> 5;
    const int lid = tid & 31;
    const int c0 = blockIdx.x << 7;    // col tile (fast dim -> A L2 reuse)
    const int r0 = blockIdx.y << 7;
    const int m0 = (wid & 1) * 64;
    const int n0 = (wid >> 1) * 64;
    const uint32_t sb = smem_u32(smem);

    float acc[4][8][4];
    #pragma unroll
    for (int i = 0; i < 4; i++)
        #pragma unroll
        for (int j = 0; j < 8; j++)
            #pragma unroll
            for (int q = 0; q < 4; q++) acc[i][j][q] = 0.f;

    load_iter(tid, sb, r0, c0, 0, Ah, Al, Wh, Wl);

    const uint32_t a_off = (uint32_t)((m0 + (lid & 15)) * ROWB + ((lid >> 4) << 4));
    const uint32_t b_off = (uint32_t)((n0 + (lid & 7) + ((lid >> 4) << 3)) * ROWB
                                      + (((lid >> 3) & 1) << 4));

    for (int it = 0; it < ITERS; it++) {
        asm volatile("cp.async.wait_group 0;");
        __syncthreads();

        if (it + 1 < ITERS)
            load_iter(tid, sb + ((it + 1) & 1) * STAGE_BYTES, r0, c0, it + 1,
                      Ah, Al, Wh, Wl);

        const uint32_t as  = sb + (it & 1) * STAGE_BYTES;
        const uint32_t bs0 = as + 128 * ROWB;
        const uint32_t bs1 = as + 256 * ROWB;

        #pragma unroll
        for (int kt = 0; kt < 4; kt++) {
            uint32_t a[4][4], b[4][4];
            #pragma unroll
            for (int mi = 0; mi < 4; mi++)
                ldmx4(a[mi], as + a_off + (uint32_t)(mi * 16 * ROWB + kt * 32));
            #pragma unroll
            for (int nj = 0; nj < 4; nj++)
                ldmx4(b[nj], bs0 + b_off + (uint32_t)(nj * 16 * ROWB + kt * 32));
            #pragma unroll
            for (int mi = 0; mi < 4; mi++)
                #pragma unroll
                for (int ni = 0; ni < 8; ni++)
                    mma16816(acc[mi][ni], a[mi],
                             b[ni >> 1][(ni & 1) * 2], b[ni >> 1][(ni & 1) * 2 + 1]);
            if (it < 8) {   // pass A: second B tile (Wl), reuse A fragments
                #pragma unroll
                for (int nj = 0; nj < 4; nj++)
                    ldmx4(b[nj], bs1 + b_off + (uint32_t)(nj * 16 * ROWB + kt * 32));
                #pragma unroll
                for (int mi = 0; mi < 4; mi++)
                    #pragma unroll
                    for (int ni = 0; ni < 8; ni++)
                        mma16816(acc[mi][ni], a[mi],
                                 b[ni >> 1][(ni & 1) * 2], b[ni >> 1][(ni & 1) * 2 + 1]);
            }
        }
    }

    // Epilogue
    float* C;
    int col0;
    if (MODE == 0) {
        const int which = c0 >> 9;
        C = (which == 0) ? C0 : (which == 1) ? C1 : C2;
        col0 = c0 & 511;
    } else {
        C = C0;
        col0 = c0;
    }
    const int g  = lid >> 2;
    const int tg = lid & 3;
    #pragma unroll
    for (int mi = 0; mi < 4; mi++) {
        #pragma unroll
        for (int ni = 0; ni < 8; ni++) {
            const int r = r0 + m0 + mi * 16 + g;
            const int c = col0 + n0 + ni * 8 + tg * 2;
            float2 v0 = make_float2(acc[mi][ni][0], acc[mi][ni][1]);
            float2 v1 = make_float2(acc[mi][ni][2], acc[mi][ni][3]);
            if (MODE == 1) {
                const float2 bb = *(const float2*)(bias + c);
                const float2 q0 = *(const float2*)(resid + ((size_t)r << 9) + c);
                const float2 q1 = *(const float2*)(resid + ((size_t)(r + 8) << 9) + c);
                v0.x += bb.x + q0.x; v0.y += bb.y + q0.y;
                v1.x += bb.x + q1.x; v1.y += bb.y + q1.y;
            }
            *(float2*)(C + ((size_t)r << 9) + c)       = v0;
            *(float2*)(C + ((size_t)(r + 8) << 9) + c) = v1;
        }
    }
}

// ---------------------------------------------------------------------------
// fp32 -> (bf16 hi, bf16 lo) splits
// ---------------------------------------------------------------------------
__global__ __launch_bounds__(256)
void wsplit_kernel(const float* __restrict__ Wq, const float* __restrict__ Wk,
                   const float* __restrict__ Wv, const float* __restrict__ Wo,
                   __nv_bfloat16* __restrict__ hi, __nv_bfloat16* __restrict__ lo)
{
    const int w = blockIdx.y;
    const float* src = (w == 0) ? Wq : (w == 1) ? Wk : (w == 2) ? Wv : Wo;
    const int i = blockIdx.x * 256 + threadIdx.x;      // < 65536
    float4 v = ((const float4*)src)[i];
    __nv_bfloat16 h0 = __float2bfloat16(v.x);
    __nv_bfloat16 h1 = __float2bfloat16(v.y);
    __nv_bfloat16 h2 = __float2bfloat16(v.z);
    __nv_bfloat16 h3 = __float2bfloat16(v.w);
    __nv_bfloat162* hp = (__nv_bfloat162*)(hi + (size_t)w * 262144);
    __nv_bfloat162* lp = (__nv_bfloat162*)(lo + (size_t)w * 262144);
    hp[2 * i]     = __nv_bfloat162(h0, h1);
    hp[2 * i + 1] = __nv_bfloat162(h2, h3);
    lp[2 * i]     = __nv_bfloat162(__float2bfloat16(v.x - __bfloat162float(h0)),
                                   __float2bfloat16(v.y - __bfloat162float(h1)));
    lp[2 * i + 1] = __nv_bfloat162(__float2bfloat16(v.z - __bfloat162float(h2)),
                                   __float2bfloat16(v.w - __bfloat162float(h3)));
}

__global__ __launch_bounds__(256)
void split_kernel(const float* __restrict__ in, __nv_bfloat16* __restrict__ hi,
                  __nv_bfloat16* __restrict__ lo, int n4)
{
    int i = blockIdx.x * 256 + threadIdx.x;
    if (i >= n4) return;
    float4 v = ((const float4*)in)[i];
    __nv_bfloat16 h0 = __float2bfloat16(v.x);
    __nv_bfloat16 h1 = __float2bfloat16(v.y);
    __nv_bfloat16 h2 = __float2bfloat16(v.z);
    __nv_bfloat16 h3 = __float2bfloat16(v.w);
    __nv_bfloat162* hp = (__nv_bfloat162*)hi;
    __nv_bfloat162* lp = (__nv_bfloat162*)lo;
    hp[2 * i]     = __nv_bfloat162(h0, h1);
    hp[2 * i + 1] = __nv_bfloat162(h2, h3);
    lp[2 * i]     = __nv_bfloat162(__float2bfloat16(v.x - __bfloat162float(h0)),
                                   __float2bfloat16(v.y - __bfloat162float(h1)));
    lp[2 * i + 1] = __nv_bfloat162(__float2bfloat16(v.z - __bfloat162float(h2)),
                                   __float2bfloat16(v.w - __bfloat162float(h3)));
}

// ---------------------------------------------------------------------------
// Attention: one CTA per (sample, 4-head group), 128 threads,
// 4x4 register tiling on packed f32x2 FMA.
// smem floats: sq[4*17*68] sk[...] sv[...] ss[4*400] sp[400]
// ---------------------------------------------------------------------------
#define AQ  0
#define AK  4624
#define AV  9248
#define ASS 13872
#define ASP 15472
#define ATT_SMEM_BYTES (15872 * 4)

__global__ __launch_bounds__(128)
void attn_kernel(const float* __restrict__ q, const float* __restrict__ k,
                 const float* __restrict__ v, const float* __restrict__ P,
                 __nv_bfloat16* __restrict__ ch, __nv_bfloat16* __restrict__ cl)
{
    extern __shared__ float sm[];
    const int n  = blockIdx.x;
    const int hg = blockIdx.y;
    const int t  = threadIdx.x;
    const size_t base = (size_t)n * D_ * M_;

    for (int f = t; f < 1088; f += 128) {
        int d = f >> 6, hc = f & 63;
        int h = hc >> 4, c4 = hc & 15;
        size_t goff = base + (size_t)d * 512 + (hg * 4 + h) * 64 + c4 * 4;
        int soff = (h * 17 + d) * 68 + c4 * 4;
        *(float4*)(sm + AQ + soff) = *(const float4*)(q + goff);
        *(float4*)(sm + AK + soff) = *(const float4*)(k + goff);
        *(float4*)(sm + AV + soff) = *(const float4*)(v + goff);
    }
    for (int f = t; f < 289; f += 128)
        sm[ASP + (f / 17) * 20 + (f % 17)] = P[f];
    __syncthreads();

    // Scores: 4 heads x 25 blocks of 4x4, packed f32x2 dot products
    if (t < 100) {
        const int h = t / 25, blk = t % 25;
        const int d0 = (blk / 5) * 4, e0 = (blk % 5) * 4;
        const float* sq = sm + AQ + (h * 17 + d0) * 68;
        const float* sk = sm + AK + (h * 17 + e0) * 68;
        unsigned long long acc2[4][4];
        #pragma unroll
        for (int i = 0; i < 4; i++)
            #pragma unroll
            for (int j = 0; j < 4; j++) acc2[i][j] = 0ull;
        #pragma unroll 8
        for (int c2 = 0; c2 < 32; c2++) {
            unsigned long long qa[4], kb[4];
            #pragma unroll
            for (int i = 0; i < 4; i++)
                qa[i] = *(const unsigned long long*)(sq + i * 68 + c2 * 2);
            #pragma unroll
            for (int j = 0; j < 4; j++)
                kb[j] = *(const unsigned long long*)(sk + j * 68 + c2 * 2);
            #pragma unroll
            for (int i = 0; i < 4; i++)
                #pragma unroll
                for (int j = 0; j < 4; j++)
                    acc2[i][j] = fma2(qa[i], kb[j], acc2[i][j]);
        }
        float* ss = sm + ASS + h * 400;
        #pragma unroll
        for (int i = 0; i < 4; i++)
            #pragma unroll
            for (int j = 0; j < 4; j++) {
                float2 p = unpack2(acc2[i][j]);
                ss[(d0 + i) * 20 + e0 + j] =
                    (p.x + p.y) * 0.125f + sm[ASP + (d0 + i) * 20 + e0 + j];
            }
    }
    __syncthreads();

    // Softmax: 4 heads x 17 rows
    if (t < 68) {
        float* row = sm + ASS + (t / 17) * 400 + (t % 17) * 20;
        float mx = -1e30f;
        #pragma unroll
        for (int e = 0; e < 17; e++) mx = fmaxf(mx, row[e]);
        float sum = 0.f;
        #pragma unroll
        for (int e = 0; e < 17; e++) {
            float ex = __expf(row[e] - mx);
            row[e] = ex;
            sum += ex;
        }
        float inv = 1.f / sum;
        #pragma unroll
        for (int e = 0; e < 17; e++) row[e] *= inv;
    }
    __syncthreads();

    // ctx: 4 heads x (5 dblk x 16 cblk), packed f32x2
    for (int task = t; task < 320; task += 128) {
        const int h = task / 80, rem = task % 80;
        const int d0 = (rem / 16) * 4, c0c = (rem % 16) * 4;
        const float* ss = sm + ASS + h * 400;
        const float* sv = sm + AV + h * 17 * 68 + c0c;
        unsigned long long acc2[4][2];
        #pragma unroll
        for (int i = 0; i < 4; i++) { acc2[i][0] = 0ull; acc2[i][1] = 0ull; }
        #pragma unroll 1
        for (int e = 0; e < 17; e++) {
            const unsigned long long v01 = *(const unsigned long long*)(sv + e * 68);
            const unsigned long long v23 = *(const unsigned long long*)(sv + e * 68 + 2);
            #pragma unroll
            for (int i = 0; i < 4; i++) {
                const float w = ss[(d0 + i) * 20 + e];
                const unsigned long long ww = pack2(w, w);
                acc2[i][0] = fma2(ww, v01, acc2[i][0]);
                acc2[i][1] = fma2(ww, v23, acc2[i][1]);
            }
        }
        #pragma unroll
        for (int i = 0; i < 4; i++) {
            const int d = d0 + i;
            if (d < 17) {
                const size_t off = base + (size_t)d * 512 + (hg * 4 + h) * 64 + c0c;
                float2 p0 = unpack2(acc2[i][0]);
                float2 p1 = unpack2(acc2[i][1]);
                float a0[4] = {p0.x, p0.y, p1.x, p1.y};
                __nv_bfloat16 hh[4], ll[4];
                #pragma unroll
                for (int j = 0; j < 4; j++) {
                    hh[j] = __float2bfloat16(a0[j]);
                    ll[j] = __float2bfloat16(a0[j] - __bfloat162float(hh[j]));
                }
                *(uint2*)(ch + off) = *(uint2*)hh;
                *(uint2*)(cl + off) = *(uint2*)ll;
            }
        }
    }
}

// ---------------------------------------------------------------------------
// In-place LayerNorm (warp per row, width 512), eps = 1e-5
// ---------------------------------------------------------------------------
__global__ __launch_bounds__(256)
void ln_kernel(float* __restrict__ out, const float* __restrict__ gamma,
               const float* __restrict__ beta)
{
    const int row  = blockIdx.x * 8 + (threadIdx.x >> 5);
    const int lane = threadIdx.x & 31;
    const size_t base = (size_t)row * 512;

    float4 vals[4];
    float sum = 0.f, sq = 0.f;
    #pragma unroll
    for (int j = 0; j < 4; j++) {
        vals[j] = *(const float4*)(out + base + (size_t)(j * 32 + lane) * 4);
        sum += vals[j].x + vals[j].y + vals[j].z + vals[j].w;
        sq  += vals[j].x * vals[j].x + vals[j].y * vals[j].y
             + vals[j].z * vals[j].z + vals[j].w * vals[j].w;
    }
    #pragma unroll
    for (int o = 16; o > 0; o >>= 1) {
        sum += __shfl_xor_sync(0xffffffffu, sum, o);
        sq  += __shfl_xor_sync(0xffffffffu, sq,  o);
    }
    const float mean = sum * (1.f / 512.f);
    const float var  = sq * (1.f / 512.f) - mean * mean;
    const float rstd = rsqrtf(var + 1e-5f);

    #pragma unroll
    for (int j = 0; j < 4; j++) {
        int c = (j * 32 + lane) * 4;
        float4 g  = *(const float4*)(gamma + c);
        float4 bb = *(const float4*)(beta + c);
        float4 v;
        v.x = (vals[j].x - mean) * rstd * g.x + bb.x;
        v.y = (vals[j].y - mean) * rstd * g.y + bb.y;
        v.z = (vals[j].z - mean) * rstd * g.z + bb.z;
        v.w = (vals[j].w - mean) * rstd * g.w + bb.w;
        *(float4*)(out + base + c) = v;
    }
}

// ---------------------------------------------------------------------------
extern "C" void kernel_launch(void* const* d_in, const int* in_sizes, int n_in,
                              void* d_out, int out_size)
{
    const float* x     = (const float*)d_in[0];
    const float* P     = (const float*)d_in[1];
    const float* Wq    = (const float*)d_in[2];
    const float* Wk    = (const float*)d_in[3];
    const float* Wv    = (const float*)d_in[4];
    const float* Wo    = (const float*)d_in[5];
    const float* bo    = (const float*)d_in[6];
    const float* gamma = (const float*)d_in[7];
    const float* beta  = (const float*)d_in[8];
    float* out = (float*)d_out;

    void *pq, *pk, *pv, *pxh, *pxl, *pch, *pcl, *pwh, *pwl;
    cudaGetSymbolAddress(&pq,  g_q);
    cudaGetSymbolAddress(&pk,  g_k);
    cudaGetSymbolAddress(&pv,  g_v);
    cudaGetSymbolAddress(&pxh, g_xh);
    cudaGetSymbolAddress(&pxl, g_xl);
    cudaGetSymbolAddress(&pch, g_ch);
    cudaGetSymbolAddress(&pcl, g_cl);
    cudaGetSymbolAddress(&pwh, g_wh);
    cudaGetSymbolAddress(&pwl, g_wl);

    __nv_bfloat16* wh = (__nv_bfloat16*)pwh;
    __nv_bfloat16* wl = (__nv_bfloat16*)pwl;

    const int dsm = 2 * STAGE_BYTES;                // 110592
    cudaFuncSetAttribute(gemm_mma<0>, cudaFuncAttributeMaxDynamicSharedMemorySize, dsm);
    cudaFuncSetAttribute(gemm_mma<1>, cudaFuncAttributeMaxDynamicSharedMemorySize, dsm);
    cudaFuncSetAttribute(attn_kernel, cudaFuncAttributeMaxDynamicSharedMemorySize,
                         ATT_SMEM_BYTES);

    // Splits
    dim3 gw(256, 4);
    wsplit_kernel<<<gw, 256>>>(Wq, Wk, Wv, Wo, wh, wl);
    const int nx4 = (int)((size_t)NROW * 512 / 4);
    split_kernel<<<(nx4 + 255) / 256, 256>>>(x, (__nv_bfloat16*)pxh,
                                             (__nv_bfloat16*)pxl, nx4);

    // Fused QKV projection: 12 col tiles over contiguous [Wq;Wk;Wv] rows
    dim3 gq(12, NROW / 128);
    gemm_mma<0><<<gq, 128, dsm>>>((const __nv_bfloat16*)pxh, (const __nv_bfloat16*)pxl,
                                  wh, wl,
                                  (float*)pq, (float*)pk, (float*)pv,
                                  nullptr, nullptr);

    dim3 ga(NSAMP, 2);
    attn_kernel<<<ga, 128, ATT_SMEM_BYTES>>>(
        (const float*)pq, (const float*)pk, (const float*)pv, P,
        (__nv_bfloat16*)pch, (__nv_bfloat16*)pcl);

    // fc_out + bias + residual
    dim3 go(4, NROW / 128);
    gemm_mma<1><<<go, 128, dsm>>>((const __nv_bfloat16*)pch, (const __nv_bfloat16*)pcl,
                                  wh + 3 * 262144, wl + 3 * 262144,
                                  out, nullptr, nullptr, bo, x);

    ln_kernel<<<NROW / 8, 256>>>(out, gamma, beta);
}